// round 15
// baseline (speedup 1.0000x reference)
#include <cuda_runtime.h>
#include <cuda_fp16.h>
#include <cstdint>

// Problem constants
#define BH_   64      // B*H = 4*16
#define M_    64      // number of blocks m = N/b
#define BB_   128     // block size b
#define D_    64      // head dim
#define N_    8192
#define SCALE_ 0.125f // 1/sqrt(64)
#define SCALE2_ 0.18033688f   // SCALE_ * log2(e)
#define EPS_   1e-6f
#define NSTEPS_ 3

// Scratch (device globals; no allocation allowed). All intermediates fp16.
__device__ __half g_Qh  [(size_t)BH_*N_*D_];       // [bh][n][d]
__device__ __half g_Kh  [(size_t)BH_*N_*D_];       // [bh][n][d]
__device__ __half g_KBAR[(size_t)BH_*BB_*M_*D_];   // [bh][l][k][d]
__device__ __half g_QBAR[(size_t)BH_*M_*BB_*D_];   // [bh][k][l][d]
__device__ __half g_LBUF[(size_t)BH_*BB_*M_*M_];   // [bh][l][i][k]
__device__ __half g_VBAR[(size_t)BH_*BB_*M_*D_];   // [bh][l][k][d]

// ---------------------------------------------------------------------------
// helpers: fp16 m16n8k16 mma + ldmatrix + cp.async
// ---------------------------------------------------------------------------
__device__ __forceinline__ uint32_t s2u(const void* p){
    return (uint32_t)__cvta_generic_to_shared(p);
}
__device__ __forceinline__ void ldsm4(uint32_t& r0, uint32_t& r1, uint32_t& r2,
                                      uint32_t& r3, uint32_t a){
    asm volatile("ldmatrix.sync.aligned.m8n8.x4.shared.b16 {%0,%1,%2,%3},[%4];"
        : "=r"(r0),"=r"(r1),"=r"(r2),"=r"(r3) : "r"(a));
}
__device__ __forceinline__ void ldsm4t(uint32_t& r0, uint32_t& r1, uint32_t& r2,
                                       uint32_t& r3, uint32_t a){
    asm volatile("ldmatrix.sync.aligned.m8n8.x4.trans.shared.b16 {%0,%1,%2,%3},[%4];"
        : "=r"(r0),"=r"(r1),"=r"(r2),"=r"(r3) : "r"(a));
}
__device__ __forceinline__ void ldsm2t(uint32_t& r0, uint32_t& r1, uint32_t a){
    asm volatile("ldmatrix.sync.aligned.m8n8.x2.trans.shared.b16 {%0,%1},[%2];"
        : "=r"(r0),"=r"(r1) : "r"(a));
}
__device__ __forceinline__ void mma16(float* c,
    uint32_t a0, uint32_t a1, uint32_t a2, uint32_t a3, uint32_t b0, uint32_t b1)
{
    asm volatile("mma.sync.aligned.m16n8k16.row.col.f32.f16.f16.f32 "
        "{%0,%1,%2,%3},{%4,%5,%6,%7},{%8,%9},{%0,%1,%2,%3};"
        : "+f"(c[0]), "+f"(c[1]), "+f"(c[2]), "+f"(c[3])
        : "r"(a0), "r"(a1), "r"(a2), "r"(a3), "r"(b0), "r"(b1));
}
__device__ __forceinline__ uint32_t packh2(float a, float b){
    __half2 h = __floats2half2_rn(a, b);
    return *reinterpret_cast<uint32_t*>(&h);
}
__device__ __forceinline__ void cpa16(uint32_t s, const void* g){
    asm volatile("cp.async.ca.shared.global [%0], [%1], 16;"
                 :: "r"(s), "l"(g) : "memory");
}
__device__ __forceinline__ void cpa_commit(){
    asm volatile("cp.async.commit_group;" ::: "memory");
}
__device__ __forceinline__ void cpa_wait0(){
    asm volatile("cp.async.wait_group 0;" ::: "memory");
}
__device__ __forceinline__ void cpa_wait1(){
    asm volatile("cp.async.wait_group 1;" ::: "memory");
}

// ---------------------------------------------------------------------------
// init: Q block -> half, K block -> half, Kbar = broadcast mean of K block
// grid (M_, BH_), 256 threads
// ---------------------------------------------------------------------------
__global__ __launch_bounds__(256)
void initqk_kernel(const float* __restrict__ Q, const float* __restrict__ K)
{
    int k  = blockIdx.x;
    int bh = blockIdx.y;
    int tid = threadIdx.x;
    int d = tid & 63;
    int g = tid >> 6;          // 0..3

    size_t off = ((size_t)bh * N_ + (size_t)k * BB_) * D_;

    const float* Qg = Q + off;
    __half* Qhg = g_Qh + off;
    for (int idx = tid; idx < 1024; idx += 256) {
        float4 v0 = *(const float4*)(Qg + idx * 8);
        float4 v1 = *(const float4*)(Qg + idx * 8 + 4);
        uint4 u;
        u.x = packh2(v0.x, v0.y); u.y = packh2(v0.z, v0.w);
        u.z = packh2(v1.x, v1.y); u.w = packh2(v1.z, v1.w);
        *(uint4*)(Qhg + idx * 8) = u;
    }

    __shared__ float red[4][64];

    const float* Kg = K + off;
    __half* Khg = g_Kh + off;
    float s = 0.f;
    for (int lp = g; lp < BB_; lp += 4) {
        float v = Kg[(size_t)lp * D_ + d];
        s += v;
        Khg[(size_t)lp * D_ + d] = __float2half_rn(v);
    }
    red[g][d] = s;
    __syncthreads();

    __shared__ __half meanh[64];
    if (tid < 64)
        meanh[tid] = __float2half_rn(
            (red[0][tid] + red[1][tid] + red[2][tid] + red[3][tid]) * (1.0f / BB_));
    __syncthreads();

    __half mv = meanh[d];
    __half* dst = g_KBAR + ((size_t)bh * BB_ * M_ + (size_t)k) * D_;
    for (int l = g; l < BB_; l += 4)
        dst[(size_t)l * M_ * D_ + d] = mv;
}

// ---------------------------------------------------------------------------
// kl: per (bh,l): S = Q_l Kbar_l^T (64x64), L = softmax_k(scale*S) IN REGISTERS,
//     Qbar = (L^T Q_l)/(w+eps) with w computed by an extra ones-column MMA.
//     grid (128, 64), 128 threads (4 warps x 16 rows)
// ---------------------------------------------------------------------------
#define KL_P 72    // half pitch (144 B rows -> conflict-free ldmatrix)

__global__ __launch_bounds__(128, 8)
void kl_kernel(int writeL)
{
    __shared__ __half Qs[64 * KL_P];
    __shared__ __half Ks[64 * KL_P];
    __shared__ __half Lh[64 * KL_P];

    int l  = blockIdx.x;
    int bh = blockIdx.y;
    int tid = threadIdx.x;
    int lane = tid & 31, wid = tid >> 5;
    int g = lane >> 2, t = lane & 3;

    const __half* Qg = g_Qh + ((size_t)bh * N_ + l) * D_;
    for (int idx = tid; idx < 64 * 8; idx += 128) {
        int i = idx >> 3, sg = idx & 7;
        cpa16(s2u(Qs + i * KL_P + sg * 8), Qg + (size_t)i * BB_ * D_ + sg * 8);
    }
    const __half* Kg = g_KBAR + ((size_t)bh * BB_ + l) * M_ * D_;
    for (int idx = tid; idx < 64 * 8; idx += 128) {
        int i = idx >> 3, sg = idx & 7;
        cpa16(s2u(Ks + i * KL_P + sg * 8), Kg + idx * 8);
    }
    // ones column in Qs padding: col 64 = 1.0h, cols 65-71 = 0 (w via MMA)
    if (tid < 64)
        *(uint4*)(Qs + tid * KL_P + 64) = make_uint4(0x00003C00u, 0u, 0u, 0u);
    cpa_commit();
    cpa_wait0();
    __syncthreads();

    int m0 = wid * 16;

    float acc[8][4];
#pragma unroll
    for (int nt = 0; nt < 8; nt++)
#pragma unroll
        for (int e = 0; e < 4; e++) acc[nt][e] = 0.f;

#pragma unroll
    for (int s = 0; s < 4; s++) {
        int k0 = s * 16;
        uint32_t a0, a1, a2, a3;
        ldsm4(a0, a1, a2, a3,
              s2u(Qs + (m0 + (lane & 15)) * KL_P + k0 + 8 * (lane >> 4)));
#pragma unroll
        for (int p = 0; p < 4; p++) {
            int n0 = p * 16;
            uint32_t b0, b1, b2, b3;
            ldsm4(b0, b1, b2, b3,
                  s2u(Ks + (n0 + (lane & 7) + 8 * (lane >> 4)) * KL_P
                         + k0 + 8 * ((lane >> 3) & 1)));
            mma16(acc[2 * p    ], a0, a1, a2, a3, b0, b1);
            mma16(acc[2 * p + 1], a0, a1, a2, a3, b2, b3);
        }
    }

    float mx0 = -1e30f, mx1 = -1e30f;
#pragma unroll
    for (int nt = 0; nt < 8; nt++) {
        mx0 = fmaxf(mx0, fmaxf(acc[nt][0], acc[nt][1]));
        mx1 = fmaxf(mx1, fmaxf(acc[nt][2], acc[nt][3]));
    }
    mx0 = fmaxf(mx0, __shfl_xor_sync(0xffffffffu, mx0, 1));
    mx0 = fmaxf(mx0, __shfl_xor_sync(0xffffffffu, mx0, 2));
    mx1 = fmaxf(mx1, __shfl_xor_sync(0xffffffffu, mx1, 1));
    mx1 = fmaxf(mx1, __shfl_xor_sync(0xffffffffu, mx1, 2));
    float nm0 = -mx0 * SCALE2_, nm1 = -mx1 * SCALE2_;
    float s0 = 0.f, s1 = 0.f;
#pragma unroll
    for (int nt = 0; nt < 8; nt++) {
        acc[nt][0] = exp2f(fmaf(acc[nt][0], SCALE2_, nm0)); s0 += acc[nt][0];
        acc[nt][1] = exp2f(fmaf(acc[nt][1], SCALE2_, nm0)); s0 += acc[nt][1];
        acc[nt][2] = exp2f(fmaf(acc[nt][2], SCALE2_, nm1)); s1 += acc[nt][2];
        acc[nt][3] = exp2f(fmaf(acc[nt][3], SCALE2_, nm1)); s1 += acc[nt][3];
    }
    s0 += __shfl_xor_sync(0xffffffffu, s0, 1);
    s0 += __shfl_xor_sync(0xffffffffu, s0, 2);
    s1 += __shfl_xor_sync(0xffffffffu, s1, 1);
    s1 += __shfl_xor_sync(0xffffffffu, s1, 2);
    float inv0 = 1.0f / s0, inv1 = 1.0f / s1;

#pragma unroll
    for (int nt = 0; nt < 8; nt++) {
        int col = nt * 8 + 2 * t;
        *(__half2*)(Lh + (m0 + g    ) * KL_P + col) =
            __floats2half2_rn(acc[nt][0] * inv0, acc[nt][1] * inv0);
        *(__half2*)(Lh + (m0 + g + 8) * KL_P + col) =
            __floats2half2_rn(acc[nt][2] * inv1, acc[nt][3] * inv1);
    }
    __syncthreads();

    if (writeL) {
        __half* Lg = g_LBUF + ((size_t)bh * BB_ + l) * M_ * M_;
        for (int idx = tid; idx < 64 * 8; idx += 128) {
            int i = idx >> 3, sg = idx & 7;
            *(uint4*)(Lg + idx * 8) = *(uint4*)(Lh + i * KL_P + sg * 8);
        }
    }

    // GEMM2 + ones-column w
    float acc2[8][4];
    float accw[4] = {0.f, 0.f, 0.f, 0.f};
#pragma unroll
    for (int nt = 0; nt < 8; nt++)
#pragma unroll
        for (int e = 0; e < 4; e++) acc2[nt][e] = 0.f;

#pragma unroll
    for (int s = 0; s < 4; s++) {
        int i0 = s * 16;
        uint32_t a0, a1, a2, a3;
        ldsm4t(a0, a1, a2, a3,
               s2u(Lh + (i0 + (lane & 7) + 8 * (lane >> 4)) * KL_P
                      + m0 + 8 * ((lane >> 3) & 1)));
#pragma unroll
        for (int p = 0; p < 4; p++) {
            int n0 = p * 16;
            uint32_t b0, b1, b2, b3;
            ldsm4t(b0, b1, b2, b3,
                   s2u(Qs + (i0 + (lane & 7) + 8 * ((lane >> 3) & 1)) * KL_P
                          + n0 + 8 * (lane >> 4)));
            mma16(acc2[2 * p    ], a0, a1, a2, a3, b0, b1);
            mma16(acc2[2 * p + 1], a0, a1, a2, a3, b2, b3);
        }
        uint32_t w0, w1;
        ldsm2t(w0, w1,
               s2u(Qs + (i0 + (lane & 7) + 8 * ((lane >> 3) & 1)) * KL_P + 64));
        mma16(accw, a0, a1, a2, a3, w0, w1);
    }

    float wr0 = __shfl_sync(0xffffffffu, accw[0], lane & 28);
    float wr1 = __shfl_sync(0xffffffffu, accw[2], lane & 28);
    float w0 = 1.0f / (wr0 + EPS_), w1 = 1.0f / (wr1 + EPS_);

    __half* Qbg = g_QBAR + (size_t)bh * M_ * BB_ * D_ + (size_t)l * D_;
#pragma unroll
    for (int nt = 0; nt < 8; nt++) {
        int dd = nt * 8 + 2 * t;
        *(__half2*)(Qbg + (size_t)(m0 + g    ) * BB_ * D_ + dd) =
            __floats2half2_rn(acc2[nt][0] * w0, acc2[nt][1] * w0);
        *(__half2*)(Qbg + (size_t)(m0 + g + 8) * BB_ * D_ + dd) =
            __floats2half2_rn(acc2[nt][2] * w1, acc2[nt][3] * w1);
    }
}

// ---------------------------------------------------------------------------
// kr v2: 512 threads, 16 warps; warp (wr,wc) owns rows wr*16..+15, col-half wc.
//   GEMM1: S = Qbar K^T (each warp 16x64).  Softmax: cross-warp-pair via smem.
//   P -> smem Ps (pitch 136).  GEMM2: out = P @ (K or V), warp does 16x32.
// grid (64, 64), dynamic smem 72KB, 2 CTAs/SM -> 32 warps.
// ---------------------------------------------------------------------------
#define KR_P 72
#define PS_P 136
#define KR_QBS_OFF 0
#define KR_KS_OFF  18432
#define KR_PS_OFF  36864              // Ps (34816B) aliases Vf (32768B)
#define KR_RED_OFF 71680              // pmax[2][128] f32, psum[2][128] f32
#define KR_SMEM_BYTES (KR_RED_OFF + 2048)

__global__ __launch_bounds__(512, 2)
void kr_kernel(const float* __restrict__ V, int last)
{
    extern __shared__ char smem[];
    __half* Qbs  = (__half*)(smem + KR_QBS_OFF);
    __half* Ks   = (__half*)(smem + KR_KS_OFF);
    __half* Ps   = (__half*)(smem + KR_PS_OFF);
    float*  Vf   = (float*)(smem + KR_PS_OFF);     // alias; consumed before Ps
    float*  pmax = (float*)(smem + KR_RED_OFF);
    float*  psum = (float*)(smem + KR_RED_OFF + 1024);

    int k  = blockIdx.x;
    int bh = blockIdx.y;
    int tid = threadIdx.x;
    int lane = tid & 31, wid = tid >> 5;
    int g = lane >> 2, t = lane & 3;
    int wr = wid >> 1, wc = wid & 1;
    int m0 = wr * 16;

    const __half* Qbg = g_QBAR + ((size_t)bh * M_ + k) * BB_ * D_;
    for (int idx = tid; idx < BB_ * 8; idx += 512) {
        int r = idx >> 3, sg = idx & 7;
        cpa16(s2u(Qbs + r * KR_P + sg * 8), Qbg + idx * 8);
    }
    const __half* Kg = g_Kh + ((size_t)bh * N_ + (size_t)k * BB_) * D_;
    for (int idx = tid; idx < BB_ * 8; idx += 512) {
        int r = idx >> 3, sg = idx & 7;
        cpa16(s2u(Ks + r * KR_P + sg * 8), Kg + idx * 8);
    }
    cpa_commit();
    if (last) {
        const float* Vg = V + ((size_t)bh * N_ + (size_t)k * BB_) * D_;
        for (int idx = tid; idx < BB_ * 16; idx += 512)
            cpa16(s2u(Vf + idx * 4), Vg + idx * 4);
        cpa_commit();
        cpa_wait1();
    } else {
        cpa_wait0();
    }
    __syncthreads();

    // GEMM1: rows m0..m0+15, cols wc*64..+63
    float acc1[8][4];
#pragma unroll
    for (int nt = 0; nt < 8; nt++)
#pragma unroll
        for (int e = 0; e < 4; e++) acc1[nt][e] = 0.f;

#pragma unroll
    for (int s = 0; s < 4; s++) {
        int k0 = s * 16;
        uint32_t a0, a1, a2, a3;
        ldsm4(a0, a1, a2, a3,
              s2u(Qbs + (m0 + (lane & 15)) * KR_P + k0 + 8 * (lane >> 4)));
#pragma unroll
        for (int p = 0; p < 4; p++) {
            int n0 = wc * 64 + p * 16;
            uint32_t b0, b1, b2, b3;
            ldsm4(b0, b1, b2, b3,
                  s2u(Ks + (n0 + (lane & 7) + 8 * (lane >> 4)) * KR_P
                         + k0 + 8 * ((lane >> 3) & 1)));
            mma16(acc1[2 * p    ], a0, a1, a2, a3, b0, b1);
            mma16(acc1[2 * p + 1], a0, a1, a2, a3, b2, b3);
        }
    }

    // row max over this warp's 64-col half; publish to smem
    float mx0 = -1e30f, mx1 = -1e30f;
#pragma unroll
    for (int nt = 0; nt < 8; nt++) {
        mx0 = fmaxf(mx0, fmaxf(acc1[nt][0], acc1[nt][1]));
        mx1 = fmaxf(mx1, fmaxf(acc1[nt][2], acc1[nt][3]));
    }
    mx0 = fmaxf(mx0, __shfl_xor_sync(0xffffffffu, mx0, 1));
    mx0 = fmaxf(mx0, __shfl_xor_sync(0xffffffffu, mx0, 2));
    mx1 = fmaxf(mx1, __shfl_xor_sync(0xffffffffu, mx1, 1));
    mx1 = fmaxf(mx1, __shfl_xor_sync(0xffffffffu, mx1, 2));
    if (t == 0) {
        pmax[wc * 128 + m0 + g    ] = mx0;
        pmax[wc * 128 + m0 + g + 8] = mx1;
    }
    __syncthreads();   // pmax visible; all GEMM1 Ks reads done

    // last iter: convert staged fp32 V into Ks (fp16)
    if (last) {
        cpa_wait0();
        for (int idx = tid; idx < BB_ * 16; idx += 512) {
            int r = idx >> 4, d4 = idx & 15;
            float4 v = *(const float4*)(Vf + r * D_ + d4 * 4);
            uint2 u; u.x = packh2(v.x, v.y); u.y = packh2(v.z, v.w);
            *(uint2*)(Ks + r * KR_P + d4 * 4) = u;
        }
    }

    float gm0 = fmaxf(pmax[m0 + g    ], pmax[128 + m0 + g    ]);
    float gm1 = fmaxf(pmax[m0 + g + 8], pmax[128 + m0 + g + 8]);
    float nm0 = -gm0 * SCALE2_, nm1 = -gm1 * SCALE2_;
    float s0 = 0.f, s1 = 0.f;
#pragma unroll
    for (int nt = 0; nt < 8; nt++) {
        acc1[nt][0] = exp2f(fmaf(acc1[nt][0], SCALE2_, nm0)); s0 += acc1[nt][0];
        acc1[nt][1] = exp2f(fmaf(acc1[nt][1], SCALE2_, nm0)); s0 += acc1[nt][1];
        acc1[nt][2] = exp2f(fmaf(acc1[nt][2], SCALE2_, nm1)); s1 += acc1[nt][2];
        acc1[nt][3] = exp2f(fmaf(acc1[nt][3], SCALE2_, nm1)); s1 += acc1[nt][3];
    }
    s0 += __shfl_xor_sync(0xffffffffu, s0, 1);
    s0 += __shfl_xor_sync(0xffffffffu, s0, 2);
    s1 += __shfl_xor_sync(0xffffffffu, s1, 1);
    s1 += __shfl_xor_sync(0xffffffffu, s1, 2);
    if (t == 0) {
        psum[wc * 128 + m0 + g    ] = s0;
        psum[wc * 128 + m0 + g + 8] = s1;
    }
    __syncthreads();   // psum visible; Vf fully consumed (Ps region now free)

    float inv0 = 1.0f / (psum[m0 + g    ] + psum[128 + m0 + g    ]);
    float inv1 = 1.0f / (psum[m0 + g + 8] + psum[128 + m0 + g + 8]);

    // probs -> Ps (row l, col l'); pitch 136 halves = 272B (conflict-free)
#pragma unroll
    for (int nt = 0; nt < 8; nt++) {
        int col = wc * 64 + nt * 8 + 2 * t;
        *(__half2*)(Ps + (m0 + g    ) * PS_P + col) =
            __floats2half2_rn(acc1[nt][0] * inv0, acc1[nt][1] * inv0);
        *(__half2*)(Ps + (m0 + g + 8) * PS_P + col) =
            __floats2half2_rn(acc1[nt][2] * inv1, acc1[nt][3] * inv1);
    }
    __syncthreads();   // Ps complete (both col halves); Ks conversion visible

    // GEMM2: out rows m0..m0+15, cols wc*32..+31; A = Ps rows, B = Ks^T
    float acc2[4][4];
#pragma unroll
    for (int nt = 0; nt < 4; nt++)
#pragma unroll
        for (int e = 0; e < 4; e++) acc2[nt][e] = 0.f;

#pragma unroll
    for (int s = 0; s < 8; s++) {
        int i0 = s * 16;
        uint32_t a0, a1, a2, a3;
        ldsm4(a0, a1, a2, a3,
              s2u(Ps + (m0 + (lane & 15)) * PS_P + i0 + 8 * (lane >> 4)));
#pragma unroll
        for (int p = 0; p < 2; p++) {
            int n0 = wc * 32 + p * 16;
            uint32_t b0, b1, b2, b3;
            ldsm4t(b0, b1, b2, b3,
                   s2u(Ks + (i0 + (lane & 7) + 8 * ((lane >> 3) & 1)) * KR_P
                          + n0 + 8 * (lane >> 4)));
            mma16(acc2[2 * p    ], a0, a1, a2, a3, b0, b1);
            mma16(acc2[2 * p + 1], a0, a1, a2, a3, b2, b3);
        }
    }

    __half* dst = (last ? g_VBAR : g_KBAR) + ((size_t)bh * BB_ * M_ + k) * D_;
#pragma unroll
    for (int nt = 0; nt < 4; nt++) {
        int dd = wc * 32 + nt * 8 + 2 * t;
        *(__half2*)(dst + (size_t)(m0 + g    ) * M_ * D_ + dd) =
            __floats2half2_rn(acc2[nt][0], acc2[nt][1]);
        *(__half2*)(dst + (size_t)(m0 + g + 8) * M_ * D_ + dd) =
            __floats2half2_rn(acc2[nt][2], acc2[nt][3]);
    }
}

// ---------------------------------------------------------------------------
// out: per (bh,l): out[i][d] = sum_kb L[i][kb] * Vbar[kb][d]
// grid (128, 64), 256 threads (8 warps 4x2)
// ---------------------------------------------------------------------------
__global__ __launch_bounds__(256)
void out_kernel(float* __restrict__ O)
{
    __shared__ __half Lsm[64 * KL_P];
    __shared__ __half Vbs[64 * KL_P];

    int l  = blockIdx.x;
    int bh = blockIdx.y;
    int tid = threadIdx.x;
    int lane = tid & 31, wid = tid >> 5;
    int g = lane >> 2, t = lane & 3;

    const __half* Lg = g_LBUF + ((size_t)bh * BB_ + l) * M_ * M_;
    for (int idx = tid; idx < 64 * 8; idx += 256) {
        int i = idx >> 3, sg = idx & 7;
        cpa16(s2u(Lsm + i * KL_P + sg * 8), Lg + idx * 8);
    }
    const __half* Vg = g_VBAR + ((size_t)bh * BB_ + l) * M_ * D_;
    for (int idx = tid; idx < 64 * 8; idx += 256) {
        int i = idx >> 3, sg = idx & 7;
        cpa16(s2u(Vbs + i * KL_P + sg * 8), Vg + idx * 8);
    }
    cpa_commit();
    cpa_wait0();
    __syncthreads();

    int wr = wid >> 1, wc = wid & 1;
    int m0 = wr * 16;

    float acc[4][4];
#pragma unroll
    for (int nt = 0; nt < 4; nt++)
#pragma unroll
        for (int e = 0; e < 4; e++) acc[nt][e] = 0.f;

#pragma unroll
    for (int s = 0; s < 4; s++) {
        int k0 = s * 16;
        uint32_t a0, a1, a2, a3;
        ldsm4(a0, a1, a2, a3,
              s2u(Lsm + (m0 + (lane & 15)) * KL_P + k0 + 8 * (lane >> 4)));
#pragma unroll
        for (int p = 0; p < 2; p++) {
            int n0 = wc * 32 + p * 16;
            uint32_t b0, b1, b2, b3;
            ldsm4t(b0, b1, b2, b3,
                   s2u(Vbs + (k0 + (lane & 7) + 8 * ((lane >> 3) & 1)) * KL_P
                           + n0 + 8 * (lane >> 4)));
            mma16(acc[2 * p    ], a0, a1, a2, a3, b0, b1);
            mma16(acc[2 * p + 1], a0, a1, a2, a3, b2, b3);
        }
    }

    float* Og = O + (size_t)bh * N_ * D_ + (size_t)l * D_;
#pragma unroll
    for (int nt = 0; nt < 4; nt++) {
        int dd = wc * 32 + nt * 8 + 2 * t;
        *(float2*)(Og + (size_t)(m0 + g    ) * BB_ * D_ + dd) =
            make_float2(acc[nt][0], acc[nt][1]);
        *(float2*)(Og + (size_t)(m0 + g + 8) * BB_ * D_ + dd) =
            make_float2(acc[nt][2], acc[nt][3]);
    }
}

// ---------------------------------------------------------------------------
extern "C" void kernel_launch(void* const* d_in, const int* in_sizes, int n_in,
                              void* d_out, int out_size)
{
    const float* Q = (const float*)d_in[0];
    const float* K = (const float*)d_in[1];
    const float* V = (const float*)d_in[2];
    float* O = (float*)d_out;

    cudaFuncSetAttribute(kr_kernel, cudaFuncAttributeMaxDynamicSharedMemorySize,
                         KR_SMEM_BYTES);

    dim3 blk512(512), blk256(256), blk128(128);
    initqk_kernel<<<dim3(M_, BH_), blk256>>>(Q, K);
    for (int t = 0; t < NSTEPS_; t++) {
        int lastFlag = (t == NSTEPS_ - 1) ? 1 : 0;
        kl_kernel<<<dim3(BB_, BH_), blk128>>>(lastFlag);
        kr_kernel<<<dim3(M_, BH_), blk512, KR_SMEM_BYTES>>>(V, lastFlag);
    }
    out_kernel<<<dim3(BB_, BH_), blk256>>>(O);
}

// round 16
// speedup vs baseline: 1.0684x; 1.0684x over previous
#include <cuda_runtime.h>
#include <cuda_fp16.h>
#include <cstdint>

// Problem constants
#define BH_   64      // B*H = 4*16
#define M_    64      // number of blocks m = N/b
#define BB_   128     // block size b
#define D_    64      // head dim
#define N_    8192
#define SCALE_ 0.125f // 1/sqrt(64)
#define SCALE2_ 0.18033688f   // SCALE_ * log2(e)
#define EPS_   1e-6f
#define NSTEPS_ 3

// Scratch (device globals; no allocation allowed). All intermediates fp16.
// g_QhT: Q in kl-friendly layout [bh][l][i][d] (contiguous per kl CTA).
__device__ __half g_QhT [(size_t)BH_*N_*D_];       // [bh][l][i][d]
__device__ __half g_Kh  [(size_t)BH_*N_*D_];       // [bh][n][d]
__device__ __half g_KBAR[(size_t)BH_*BB_*M_*D_];   // [bh][l][k][d]
__device__ __half g_QBAR[(size_t)BH_*M_*BB_*D_];   // [bh][k][l][d]
__device__ __half g_LBUF[(size_t)BH_*BB_*M_*M_];   // [bh][l][i][k]
__device__ __half g_VBAR[(size_t)BH_*BB_*M_*D_];   // [bh][l][k][d]

// ---------------------------------------------------------------------------
// helpers: fp16 m16n8k16 mma + ldmatrix + cp.async
// ---------------------------------------------------------------------------
__device__ __forceinline__ uint32_t s2u(const void* p){
    return (uint32_t)__cvta_generic_to_shared(p);
}
__device__ __forceinline__ void ldsm4(uint32_t& r0, uint32_t& r1, uint32_t& r2,
                                      uint32_t& r3, uint32_t a){
    asm volatile("ldmatrix.sync.aligned.m8n8.x4.shared.b16 {%0,%1,%2,%3},[%4];"
        : "=r"(r0),"=r"(r1),"=r"(r2),"=r"(r3) : "r"(a));
}
__device__ __forceinline__ void ldsm4t(uint32_t& r0, uint32_t& r1, uint32_t& r2,
                                       uint32_t& r3, uint32_t a){
    asm volatile("ldmatrix.sync.aligned.m8n8.x4.trans.shared.b16 {%0,%1,%2,%3},[%4];"
        : "=r"(r0),"=r"(r1),"=r"(r2),"=r"(r3) : "r"(a));
}
__device__ __forceinline__ void ldsm2t(uint32_t& r0, uint32_t& r1, uint32_t a){
    asm volatile("ldmatrix.sync.aligned.m8n8.x2.trans.shared.b16 {%0,%1},[%2];"
        : "=r"(r0),"=r"(r1) : "r"(a));
}
__device__ __forceinline__ void mma16(float* c,
    uint32_t a0, uint32_t a1, uint32_t a2, uint32_t a3, uint32_t b0, uint32_t b1)
{
    asm volatile("mma.sync.aligned.m16n8k16.row.col.f32.f16.f16.f32 "
        "{%0,%1,%2,%3},{%4,%5,%6,%7},{%8,%9},{%0,%1,%2,%3};"
        : "+f"(c[0]), "+f"(c[1]), "+f"(c[2]), "+f"(c[3])
        : "r"(a0), "r"(a1), "r"(a2), "r"(a3), "r"(b0), "r"(b1));
}
__device__ __forceinline__ uint32_t packh2(float a, float b){
    __half2 h = __floats2half2_rn(a, b);
    return *reinterpret_cast<uint32_t*>(&h);
}
__device__ __forceinline__ void cpa16(uint32_t s, const void* g){
    asm volatile("cp.async.ca.shared.global [%0], [%1], 16;"
                 :: "r"(s), "l"(g) : "memory");
}
__device__ __forceinline__ void cpa_commit(){
    asm volatile("cp.async.commit_group;" ::: "memory");
}
__device__ __forceinline__ void cpa_wait0(){
    asm volatile("cp.async.wait_group 0;" ::: "memory");
}
__device__ __forceinline__ void cpa_wait1(){
    asm volatile("cp.async.wait_group 1;" ::: "memory");
}

// ---------------------------------------------------------------------------
// init: Q block -> half TRANSPOSED to [bh][l][i][d], K block -> half,
//       Kbar = broadcast mean of K block.  grid (M_, BH_), 256 threads
// Block (k,bh) covers n in [k*BB_, (k+1)*BB_) i.e. i = k, all l.
// ---------------------------------------------------------------------------
__global__ __launch_bounds__(256)
void initqk_kernel(const float* __restrict__ Q, const float* __restrict__ K)
{
    int k  = blockIdx.x;
    int bh = blockIdx.y;
    int tid = threadIdx.x;
    int d = tid & 63;
    int g = tid >> 6;          // 0..3

    size_t off = ((size_t)bh * N_ + (size_t)k * BB_) * D_;

    // Q convert + transpose: row l (local) -> g_QhT[bh][l][k][d]
    const float* Qg = Q + off;
    __half* QhT = g_QhT + ((size_t)bh * BB_ * M_ + (size_t)k) * D_;
    for (int idx = tid; idx < 1024; idx += 256) {
        int lp = idx >> 3, d8 = (idx & 7) * 8;
        float4 v0 = *(const float4*)(Qg + lp * D_ + d8);
        float4 v1 = *(const float4*)(Qg + lp * D_ + d8 + 4);
        uint4 u;
        u.x = packh2(v0.x, v0.y); u.y = packh2(v0.z, v0.w);
        u.z = packh2(v1.x, v1.y); u.w = packh2(v1.z, v1.w);
        *(uint4*)(QhT + (size_t)lp * M_ * D_ + d8) = u;
    }

    __shared__ float red[4][64];

    const float* Kg = K + off;
    __half* Khg = g_Kh + off;
    float s = 0.f;
    for (int lp = g; lp < BB_; lp += 4) {
        float v = Kg[(size_t)lp * D_ + d];
        s += v;
        Khg[(size_t)lp * D_ + d] = __float2half_rn(v);
    }
    red[g][d] = s;
    __syncthreads();

    __shared__ __half meanh[64];
    if (tid < 64)
        meanh[tid] = __float2half_rn(
            (red[0][tid] + red[1][tid] + red[2][tid] + red[3][tid]) * (1.0f / BB_));
    __syncthreads();

    __half mv = meanh[d];
    __half* dst = g_KBAR + ((size_t)bh * BB_ * M_ + (size_t)k) * D_;
    for (int l = g; l < BB_; l += 4)
        dst[(size_t)l * M_ * D_ + d] = mv;
}

// ---------------------------------------------------------------------------
// kl: per (bh,l): S = Q_l Kbar_l^T (64x64), L = softmax_k(scale*S) IN REGISTERS,
//     Qbar = (L^T Q_l)/(w+eps) with w computed by an extra ones-column MMA.
//     grid (128, 64), 128 threads (4 warps x 16 rows)
// ---------------------------------------------------------------------------
#define KL_P 72    // half pitch (144 B rows -> conflict-free ldmatrix)

__global__ __launch_bounds__(128, 8)
void kl_kernel(int writeL)
{
    __shared__ __half Qs[64 * KL_P];
    __shared__ __half Ks[64 * KL_P];
    __shared__ __half Lh[64 * KL_P];

    int l  = blockIdx.x;
    int bh = blockIdx.y;
    int tid = threadIdx.x;
    int lane = tid & 31, wid = tid >> 5;
    int g = lane >> 2, t = lane & 3;

    // Q tile: fully contiguous 8KB in g_QhT
    const __half* Qg = g_QhT + ((size_t)bh * BB_ + l) * M_ * D_;
    for (int idx = tid; idx < 64 * 8; idx += 128) {
        int i = idx >> 3, sg = idx & 7;
        cpa16(s2u(Qs + i * KL_P + sg * 8), Qg + idx * 8);
    }
    const __half* Kg = g_KBAR + ((size_t)bh * BB_ + l) * M_ * D_;
    for (int idx = tid; idx < 64 * 8; idx += 128) {
        int i = idx >> 3, sg = idx & 7;
        cpa16(s2u(Ks + i * KL_P + sg * 8), Kg + idx * 8);
    }
    // ones column in Qs padding: col 64 = 1.0h, cols 65-71 = 0 (w via MMA)
    if (tid < 64)
        *(uint4*)(Qs + tid * KL_P + 64) = make_uint4(0x00003C00u, 0u, 0u, 0u);
    cpa_commit();
    cpa_wait0();
    __syncthreads();

    int m0 = wid * 16;

    float acc[8][4];
#pragma unroll
    for (int nt = 0; nt < 8; nt++)
#pragma unroll
        for (int e = 0; e < 4; e++) acc[nt][e] = 0.f;

#pragma unroll
    for (int s = 0; s < 4; s++) {
        int k0 = s * 16;
        uint32_t a0, a1, a2, a3;
        ldsm4(a0, a1, a2, a3,
              s2u(Qs + (m0 + (lane & 15)) * KL_P + k0 + 8 * (lane >> 4)));
#pragma unroll
        for (int p = 0; p < 4; p++) {
            int n0 = p * 16;
            uint32_t b0, b1, b2, b3;
            ldsm4(b0, b1, b2, b3,
                  s2u(Ks + (n0 + (lane & 7) + 8 * (lane >> 4)) * KL_P
                         + k0 + 8 * ((lane >> 3) & 1)));
            mma16(acc[2 * p    ], a0, a1, a2, a3, b0, b1);
            mma16(acc[2 * p + 1], a0, a1, a2, a3, b2, b3);
        }
    }

    float mx0 = -1e30f, mx1 = -1e30f;
#pragma unroll
    for (int nt = 0; nt < 8; nt++) {
        mx0 = fmaxf(mx0, fmaxf(acc[nt][0], acc[nt][1]));
        mx1 = fmaxf(mx1, fmaxf(acc[nt][2], acc[nt][3]));
    }
    mx0 = fmaxf(mx0, __shfl_xor_sync(0xffffffffu, mx0, 1));
    mx0 = fmaxf(mx0, __shfl_xor_sync(0xffffffffu, mx0, 2));
    mx1 = fmaxf(mx1, __shfl_xor_sync(0xffffffffu, mx1, 1));
    mx1 = fmaxf(mx1, __shfl_xor_sync(0xffffffffu, mx1, 2));
    float nm0 = -mx0 * SCALE2_, nm1 = -mx1 * SCALE2_;
    float s0 = 0.f, s1 = 0.f;
#pragma unroll
    for (int nt = 0; nt < 8; nt++) {
        acc[nt][0] = exp2f(fmaf(acc[nt][0], SCALE2_, nm0)); s0 += acc[nt][0];
        acc[nt][1] = exp2f(fmaf(acc[nt][1], SCALE2_, nm0)); s0 += acc[nt][1];
        acc[nt][2] = exp2f(fmaf(acc[nt][2], SCALE2_, nm1)); s1 += acc[nt][2];
        acc[nt][3] = exp2f(fmaf(acc[nt][3], SCALE2_, nm1)); s1 += acc[nt][3];
    }
    s0 += __shfl_xor_sync(0xffffffffu, s0, 1);
    s0 += __shfl_xor_sync(0xffffffffu, s0, 2);
    s1 += __shfl_xor_sync(0xffffffffu, s1, 1);
    s1 += __shfl_xor_sync(0xffffffffu, s1, 2);
    float inv0 = 1.0f / s0, inv1 = 1.0f / s1;

#pragma unroll
    for (int nt = 0; nt < 8; nt++) {
        int col = nt * 8 + 2 * t;
        *(__half2*)(Lh + (m0 + g    ) * KL_P + col) =
            __floats2half2_rn(acc[nt][0] * inv0, acc[nt][1] * inv0);
        *(__half2*)(Lh + (m0 + g + 8) * KL_P + col) =
            __floats2half2_rn(acc[nt][2] * inv1, acc[nt][3] * inv1);
    }
    __syncthreads();

    if (writeL) {
        __half* Lg = g_LBUF + ((size_t)bh * BB_ + l) * M_ * M_;
        for (int idx = tid; idx < 64 * 8; idx += 128) {
            int i = idx >> 3, sg = idx & 7;
            *(uint4*)(Lg + idx * 8) = *(uint4*)(Lh + i * KL_P + sg * 8);
        }
    }

    // GEMM2 + ones-column w
    float acc2[8][4];
    float accw[4] = {0.f, 0.f, 0.f, 0.f};
#pragma unroll
    for (int nt = 0; nt < 8; nt++)
#pragma unroll
        for (int e = 0; e < 4; e++) acc2[nt][e] = 0.f;

#pragma unroll
    for (int s = 0; s < 4; s++) {
        int i0 = s * 16;
        uint32_t a0, a1, a2, a3;
        ldsm4t(a0, a1, a2, a3,
               s2u(Lh + (i0 + (lane & 7) + 8 * (lane >> 4)) * KL_P
                      + m0 + 8 * ((lane >> 3) & 1)));
#pragma unroll
        for (int p = 0; p < 4; p++) {
            int n0 = p * 16;
            uint32_t b0, b1, b2, b3;
            ldsm4t(b0, b1, b2, b3,
                   s2u(Qs + (i0 + (lane & 7) + 8 * ((lane >> 3) & 1)) * KL_P
                          + n0 + 8 * (lane >> 4)));
            mma16(acc2[2 * p    ], a0, a1, a2, a3, b0, b1);
            mma16(acc2[2 * p + 1], a0, a1, a2, a3, b2, b3);
        }
        uint32_t w0, w1;
        ldsm2t(w0, w1,
               s2u(Qs + (i0 + (lane & 7) + 8 * ((lane >> 3) & 1)) * KL_P + 64));
        mma16(accw, a0, a1, a2, a3, w0, w1);
    }

    float wr0 = __shfl_sync(0xffffffffu, accw[0], lane & 28);
    float wr1 = __shfl_sync(0xffffffffu, accw[2], lane & 28);
    float w0 = 1.0f / (wr0 + EPS_), w1 = 1.0f / (wr1 + EPS_);

    __half* Qbg = g_QBAR + (size_t)bh * M_ * BB_ * D_ + (size_t)l * D_;
#pragma unroll
    for (int nt = 0; nt < 8; nt++) {
        int dd = nt * 8 + 2 * t;
        *(__half2*)(Qbg + (size_t)(m0 + g    ) * BB_ * D_ + dd) =
            __floats2half2_rn(acc2[nt][0] * w0, acc2[nt][1] * w0);
        *(__half2*)(Qbg + (size_t)(m0 + g + 8) * BB_ * D_ + dd) =
            __floats2half2_rn(acc2[nt][2] * w1, acc2[nt][3] * w1);
    }
}

// ---------------------------------------------------------------------------
// kr (round-14 design, reverted): 256 threads, 8 warps, P in registers,
//     V prefetched via second cp.async group into fp32 staging smem.
// grid (64, 64)
// ---------------------------------------------------------------------------
#define KR_P 72

__global__ __launch_bounds__(256, 3)
void kr_kernel(const float* __restrict__ V, int last)
{
    __shared__ __half Qbs[BB_ * KR_P];
    __shared__ __half Ks [BB_ * KR_P];   // K_k; overwritten by V_k on last iter
    __shared__ float  Vf [BB_ * D_];     // fp32 V staging (last iter only)

    int k  = blockIdx.x;
    int bh = blockIdx.y;
    int tid = threadIdx.x;
    int lane = tid & 31, wid = tid >> 5;
    int g = lane >> 2, t = lane & 3;

    const __half* Qbg = g_QBAR + ((size_t)bh * M_ + k) * BB_ * D_;
    for (int idx = tid; idx < BB_ * 8; idx += 256) {
        int r = idx >> 3, sg = idx & 7;
        cpa16(s2u(Qbs + r * KR_P + sg * 8), Qbg + idx * 8);
    }
    const __half* Kg = g_Kh + ((size_t)bh * N_ + (size_t)k * BB_) * D_;
    for (int idx = tid; idx < BB_ * 8; idx += 256) {
        int r = idx >> 3, sg = idx & 7;
        cpa16(s2u(Ks + r * KR_P + sg * 8), Kg + idx * 8);
    }
    cpa_commit();
    if (last) {
        const float* Vg = V + ((size_t)bh * N_ + (size_t)k * BB_) * D_;
        for (int idx = tid; idx < BB_ * 16; idx += 256)
            cpa16(s2u(Vf + idx * 4), Vg + idx * 4);
        cpa_commit();
        cpa_wait1();
    } else {
        cpa_wait0();
    }
    __syncthreads();

    int m0 = wid * 16;

    float acc1[16][4];
#pragma unroll
    for (int nt = 0; nt < 16; nt++)
#pragma unroll
        for (int e = 0; e < 4; e++) acc1[nt][e] = 0.f;

#pragma unroll
    for (int s = 0; s < 4; s++) {
        int k0 = s * 16;
        uint32_t a0, a1, a2, a3;
        ldsm4(a0, a1, a2, a3,
              s2u(Qbs + (m0 + (lane & 15)) * KR_P + k0 + 8 * (lane >> 4)));
#pragma unroll
        for (int p = 0; p < 8; p++) {
            int n0 = p * 16;
            uint32_t b0, b1, b2, b3;
            ldsm4(b0, b1, b2, b3,
                  s2u(Ks + (n0 + (lane & 7) + 8 * (lane >> 4)) * KR_P
                         + k0 + 8 * ((lane >> 3) & 1)));
            mma16(acc1[2 * p    ], a0, a1, a2, a3, b0, b1);
            mma16(acc1[2 * p + 1], a0, a1, a2, a3, b2, b3);
        }
    }

    if (last) {
        __syncthreads();       // all warps done reading Ks
        cpa_wait0();           // V staging complete
        for (int idx = tid; idx < BB_ * 16; idx += 256) {
            int r = idx >> 4, d4 = idx & 15;
            float4 v = *(const float4*)(Vf + r * D_ + d4 * 4);
            uint2 u; u.x = packh2(v.x, v.y); u.y = packh2(v.z, v.w);
            *(uint2*)(Ks + r * KR_P + d4 * 4) = u;
        }
        __syncthreads();
    }

    float mx0 = -1e30f, mx1 = -1e30f;
#pragma unroll
    for (int nt = 0; nt < 16; nt++) {
        mx0 = fmaxf(mx0, fmaxf(acc1[nt][0], acc1[nt][1]));
        mx1 = fmaxf(mx1, fmaxf(acc1[nt][2], acc1[nt][3]));
    }
    mx0 = fmaxf(mx0, __shfl_xor_sync(0xffffffffu, mx0, 1));
    mx0 = fmaxf(mx0, __shfl_xor_sync(0xffffffffu, mx0, 2));
    mx1 = fmaxf(mx1, __shfl_xor_sync(0xffffffffu, mx1, 1));
    mx1 = fmaxf(mx1, __shfl_xor_sync(0xffffffffu, mx1, 2));
    float nm0 = -mx0 * SCALE2_, nm1 = -mx1 * SCALE2_;
    float s0 = 0.f, s1 = 0.f;
#pragma unroll
    for (int nt = 0; nt < 16; nt++) {
        acc1[nt][0] = exp2f(fmaf(acc1[nt][0], SCALE2_, nm0)); s0 += acc1[nt][0];
        acc1[nt][1] = exp2f(fmaf(acc1[nt][1], SCALE2_, nm0)); s0 += acc1[nt][1];
        acc1[nt][2] = exp2f(fmaf(acc1[nt][2], SCALE2_, nm1)); s1 += acc1[nt][2];
        acc1[nt][3] = exp2f(fmaf(acc1[nt][3], SCALE2_, nm1)); s1 += acc1[nt][3];
    }
    s0 += __shfl_xor_sync(0xffffffffu, s0, 1);
    s0 += __shfl_xor_sync(0xffffffffu, s0, 2);
    s1 += __shfl_xor_sync(0xffffffffu, s1, 1);
    s1 += __shfl_xor_sync(0xffffffffu, s1, 2);
    float inv0 = 1.0f / s0, inv1 = 1.0f / s1;

    uint32_t prob[8][4];
#pragma unroll
    for (int s = 0; s < 8; s++) {
        prob[s][0] = packh2(acc1[2*s  ][0] * inv0, acc1[2*s  ][1] * inv0);
        prob[s][1] = packh2(acc1[2*s  ][2] * inv1, acc1[2*s  ][3] * inv1);
        prob[s][2] = packh2(acc1[2*s+1][0] * inv0, acc1[2*s+1][1] * inv0);
        prob[s][3] = packh2(acc1[2*s+1][2] * inv1, acc1[2*s+1][3] * inv1);
    }

    float acc2[8][4];
#pragma unroll
    for (int nt = 0; nt < 8; nt++)
#pragma unroll
        for (int e = 0; e < 4; e++) acc2[nt][e] = 0.f;

#pragma unroll
    for (int s = 0; s < 8; s++) {
        int i0 = s * 16;
#pragma unroll
        for (int p = 0; p < 4; p++) {
            int n0 = p * 16;
            uint32_t b0, b1, b2, b3;
            ldsm4t(b0, b1, b2, b3,
                   s2u(Ks + (i0 + (lane & 7) + 8 * ((lane >> 3) & 1)) * KR_P
                          + n0 + 8 * (lane >> 4)));
            mma16(acc2[2 * p    ], prob[s][0], prob[s][1], prob[s][2], prob[s][3], b0, b1);
            mma16(acc2[2 * p + 1], prob[s][0], prob[s][1], prob[s][2], prob[s][3], b2, b3);
        }
    }

    __half* dst = (last ? g_VBAR : g_KBAR) + ((size_t)bh * BB_ * M_ + k) * D_;
#pragma unroll
    for (int nt = 0; nt < 8; nt++) {
        int dd = nt * 8 + 2 * t;
        *(__half2*)(dst + (size_t)(m0 + g    ) * M_ * D_ + dd) =
            __floats2half2_rn(acc2[nt][0], acc2[nt][1]);
        *(__half2*)(dst + (size_t)(m0 + g + 8) * M_ * D_ + dd) =
            __floats2half2_rn(acc2[nt][2], acc2[nt][3]);
    }
}

// ---------------------------------------------------------------------------
// out: per (bh,l): out[i][d] = sum_kb L[i][kb] * Vbar[kb][d]
// grid (128, 64), 256 threads (8 warps 4x2)
// ---------------------------------------------------------------------------
__global__ __launch_bounds__(256)
void out_kernel(float* __restrict__ O)
{
    __shared__ __half Lsm[64 * KL_P];
    __shared__ __half Vbs[64 * KL_P];

    int l  = blockIdx.x;
    int bh = blockIdx.y;
    int tid = threadIdx.x;
    int lane = tid & 31, wid = tid >> 5;
    int g = lane >> 2, t = lane & 3;

    const __half* Lg = g_LBUF + ((size_t)bh * BB_ + l) * M_ * M_;
    for (int idx = tid; idx < 64 * 8; idx += 256) {
        int i = idx >> 3, sg = idx & 7;
        cpa16(s2u(Lsm + i * KL_P + sg * 8), Lg + idx * 8);
    }
    const __half* Vg = g_VBAR + ((size_t)bh * BB_ + l) * M_ * D_;
    for (int idx = tid; idx < 64 * 8; idx += 256) {
        int i = idx >> 3, sg = idx & 7;
        cpa16(s2u(Vbs + i * KL_P + sg * 8), Vg + idx * 8);
    }
    cpa_commit();
    cpa_wait0();
    __syncthreads();

    int wr = wid >> 1, wc = wid & 1;
    int m0 = wr * 16;

    float acc[4][4];
#pragma unroll
    for (int nt = 0; nt < 4; nt++)
#pragma unroll
        for (int e = 0; e < 4; e++) acc[nt][e] = 0.f;

#pragma unroll
    for (int s = 0; s < 4; s++) {
        int k0 = s * 16;
        uint32_t a0, a1, a2, a3;
        ldsm4(a0, a1, a2, a3,
              s2u(Lsm + (m0 + (lane & 15)) * KL_P + k0 + 8 * (lane >> 4)));
#pragma unroll
        for (int p = 0; p < 2; p++) {
            int n0 = wc * 32 + p * 16;
            uint32_t b0, b1, b2, b3;
            ldsm4t(b0, b1, b2, b3,
                   s2u(Vbs + (k0 + (lane & 7) + 8 * ((lane >> 3) & 1)) * KL_P
                           + n0 + 8 * (lane >> 4)));
            mma16(acc[2 * p    ], a0, a1, a2, a3, b0, b1);
            mma16(acc[2 * p + 1], a0, a1, a2, a3, b2, b3);
        }
    }

    float* Og = O + (size_t)bh * N_ * D_ + (size_t)l * D_;
#pragma unroll
    for (int nt = 0; nt < 4; nt++) {
        int dd = wc * 32 + nt * 8 + 2 * t;
        *(float2*)(Og + (size_t)(m0 + g    ) * BB_ * D_ + dd) =
            make_float2(acc[nt][0], acc[nt][1]);
        *(float2*)(Og + (size_t)(m0 + g + 8) * BB_ * D_ + dd) =
            make_float2(acc[nt][2], acc[nt][3]);
    }
}

// ---------------------------------------------------------------------------
extern "C" void kernel_launch(void* const* d_in, const int* in_sizes, int n_in,
                              void* d_out, int out_size)
{
    const float* Q = (const float*)d_in[0];
    const float* K = (const float*)d_in[1];
    const float* V = (const float*)d_in[2];
    float* O = (float*)d_out;

    dim3 blk256(256), blk128(128);
    initqk_kernel<<<dim3(M_, BH_), blk256>>>(Q, K);
    for (int t = 0; t < NSTEPS_; t++) {
        int lastFlag = (t == NSTEPS_ - 1) ? 1 : 0;
        kl_kernel<<<dim3(BB_, BH_), blk128>>>(lastFlag);
        kr_kernel<<<dim3(M_, BH_), blk256>>>(V, lastFlag);
    }
    out_kernel<<<dim3(BB_, BH_), blk256>>>(O);
}

// round 17
// speedup vs baseline: 1.0839x; 1.0144x over previous
#include <cuda_runtime.h>
#include <cuda_fp16.h>
#include <cstdint>

// Problem constants
#define BH_   64      // B*H = 4*16
#define M_    64      // number of blocks m = N/b
#define BB_   128     // block size b
#define D_    64      // head dim
#define N_    8192
#define SCALE_ 0.125f // 1/sqrt(64)
#define SCALE2_ 0.18033688f   // SCALE_ * log2(e)
#define EPS_   1e-6f
#define NSTEPS_ 3

// Scratch (device globals; no allocation allowed). All intermediates fp16.
// g_QhT: Q in kl-friendly layout [bh][l][i][d] (contiguous per kl CTA).
__device__ __half g_QhT [(size_t)BH_*N_*D_];       // [bh][l][i][d]
__device__ __half g_Kh  [(size_t)BH_*N_*D_];       // [bh][n][d]
__device__ __half g_KBAR[(size_t)BH_*BB_*M_*D_];   // [bh][l][k][d]
__device__ __half g_QBAR[(size_t)BH_*M_*BB_*D_];   // [bh][k][l][d]
__device__ __half g_LBUF[(size_t)BH_*BB_*M_*M_];   // [bh][l][i][k]
__device__ __half g_VBAR[(size_t)BH_*BB_*M_*D_];   // [bh][l][k][d]

// ---------------------------------------------------------------------------
// helpers: fp16 m16n8k16 mma + ldmatrix + cp.async
// ---------------------------------------------------------------------------
__device__ __forceinline__ uint32_t s2u(const void* p){
    return (uint32_t)__cvta_generic_to_shared(p);
}
__device__ __forceinline__ void ldsm4(uint32_t& r0, uint32_t& r1, uint32_t& r2,
                                      uint32_t& r3, uint32_t a){
    asm volatile("ldmatrix.sync.aligned.m8n8.x4.shared.b16 {%0,%1,%2,%3},[%4];"
        : "=r"(r0),"=r"(r1),"=r"(r2),"=r"(r3) : "r"(a));
}
__device__ __forceinline__ void ldsm4t(uint32_t& r0, uint32_t& r1, uint32_t& r2,
                                       uint32_t& r3, uint32_t a){
    asm volatile("ldmatrix.sync.aligned.m8n8.x4.trans.shared.b16 {%0,%1,%2,%3},[%4];"
        : "=r"(r0),"=r"(r1),"=r"(r2),"=r"(r3) : "r"(a));
}
__device__ __forceinline__ void ldsm2t(uint32_t& r0, uint32_t& r1, uint32_t a){
    asm volatile("ldmatrix.sync.aligned.m8n8.x2.trans.shared.b16 {%0,%1},[%2];"
        : "=r"(r0),"=r"(r1) : "r"(a));
}
__device__ __forceinline__ void mma16(float* c,
    uint32_t a0, uint32_t a1, uint32_t a2, uint32_t a3, uint32_t b0, uint32_t b1)
{
    asm volatile("mma.sync.aligned.m16n8k16.row.col.f32.f16.f16.f32 "
        "{%0,%1,%2,%3},{%4,%5,%6,%7},{%8,%9},{%0,%1,%2,%3};"
        : "+f"(c[0]), "+f"(c[1]), "+f"(c[2]), "+f"(c[3])
        : "r"(a0), "r"(a1), "r"(a2), "r"(a3), "r"(b0), "r"(b1));
}
__device__ __forceinline__ uint32_t packh2(float a, float b){
    __half2 h = __floats2half2_rn(a, b);
    return *reinterpret_cast<uint32_t*>(&h);
}
__device__ __forceinline__ void cpa16(uint32_t s, const void* g){
    asm volatile("cp.async.ca.shared.global [%0], [%1], 16;"
                 :: "r"(s), "l"(g) : "memory");
}
__device__ __forceinline__ void cpa_commit(){
    asm volatile("cp.async.commit_group;" ::: "memory");
}
__device__ __forceinline__ void cpa_wait0(){
    asm volatile("cp.async.wait_group 0;" ::: "memory");
}
__device__ __forceinline__ void cpa_wait1(){
    asm volatile("cp.async.wait_group 1;" ::: "memory");
}

// ---------------------------------------------------------------------------
// init: Q block -> half TRANSPOSED to [bh][l][i][d], K block -> half,
//       Kbar = broadcast mean of K block.  grid (M_, BH_), 256 threads
// ---------------------------------------------------------------------------
__global__ __launch_bounds__(256)
void initqk_kernel(const float* __restrict__ Q, const float* __restrict__ K)
{
    int k  = blockIdx.x;
    int bh = blockIdx.y;
    int tid = threadIdx.x;
    int d = tid & 63;
    int g = tid >> 6;          // 0..3

    size_t off = ((size_t)bh * N_ + (size_t)k * BB_) * D_;

    // Q convert + transpose: row l (local) -> g_QhT[bh][l][k][d]
    const float* Qg = Q + off;
    __half* QhT = g_QhT + ((size_t)bh * BB_ * M_ + (size_t)k) * D_;
    for (int idx = tid; idx < 1024; idx += 256) {
        int lp = idx >> 3, d8 = (idx & 7) * 8;
        float4 v0 = *(const float4*)(Qg + lp * D_ + d8);
        float4 v1 = *(const float4*)(Qg + lp * D_ + d8 + 4);
        uint4 u;
        u.x = packh2(v0.x, v0.y); u.y = packh2(v0.z, v0.w);
        u.z = packh2(v1.x, v1.y); u.w = packh2(v1.z, v1.w);
        *(uint4*)(QhT + (size_t)lp * M_ * D_ + d8) = u;
    }

    __shared__ float red[4][64];

    const float* Kg = K + off;
    __half* Khg = g_Kh + off;
    float s = 0.f;
    for (int lp = g; lp < BB_; lp += 4) {
        float v = Kg[(size_t)lp * D_ + d];
        s += v;
        Khg[(size_t)lp * D_ + d] = __float2half_rn(v);
    }
    red[g][d] = s;
    __syncthreads();

    __shared__ __half meanh[64];
    if (tid < 64)
        meanh[tid] = __float2half_rn(
            (red[0][tid] + red[1][tid] + red[2][tid] + red[3][tid]) * (1.0f / BB_));
    __syncthreads();

    __half mv = meanh[d];
    __half* dst = g_KBAR + ((size_t)bh * BB_ * M_ + (size_t)k) * D_;
    for (int l = g; l < BB_; l += 4)
        dst[(size_t)l * M_ * D_ + d] = mv;
}

// ---------------------------------------------------------------------------
// kl: per (bh,l): S = Q_l Kbar_l^T (64x64), L = softmax_k(scale*S) IN REGISTERS,
//     Qbar = (L^T Q_l)/(w+eps) with w computed by an extra ones-column MMA.
//     grid (128, 64), 128 threads (4 warps x 16 rows).
//     Lh (prob tile) ALIASES Ks (Kbar dead after GEMM1); smem 19KB.
// ---------------------------------------------------------------------------
#define KL_P 72    // half pitch (144 B rows -> conflict-free ldmatrix)

__global__ __launch_bounds__(128, 9)
void kl_kernel(int writeL)
{
    __shared__ __half Qs[64 * KL_P];
    __shared__ __half Ks[64 * KL_P];   // Kbar for GEMM1; reused as Lh after
    __half* Lh = Ks;

    int l  = blockIdx.x;
    int bh = blockIdx.y;
    int tid = threadIdx.x;
    int lane = tid & 31, wid = tid >> 5;
    int g = lane >> 2, t = lane & 3;

    // Q tile: fully contiguous 8KB in g_QhT
    const __half* Qg = g_QhT + ((size_t)bh * BB_ + l) * M_ * D_;
    for (int idx = tid; idx < 64 * 8; idx += 128) {
        int i = idx >> 3, sg = idx & 7;
        cpa16(s2u(Qs + i * KL_P + sg * 8), Qg + idx * 8);
    }
    const __half* Kg = g_KBAR + ((size_t)bh * BB_ + l) * M_ * D_;
    for (int idx = tid; idx < 64 * 8; idx += 128) {
        int i = idx >> 3, sg = idx & 7;
        cpa16(s2u(Ks + i * KL_P + sg * 8), Kg + idx * 8);
    }
    // ones column in Qs padding: col 64 = 1.0h, cols 65-71 = 0 (w via MMA)
    if (tid < 64)
        *(uint4*)(Qs + tid * KL_P + 64) = make_uint4(0x00003C00u, 0u, 0u, 0u);
    cpa_commit();
    cpa_wait0();
    __syncthreads();

    int m0 = wid * 16;

    float acc[8][4];
#pragma unroll
    for (int nt = 0; nt < 8; nt++)
#pragma unroll
        for (int e = 0; e < 4; e++) acc[nt][e] = 0.f;

#pragma unroll
    for (int s = 0; s < 4; s++) {
        int k0 = s * 16;
        uint32_t a0, a1, a2, a3;
        ldsm4(a0, a1, a2, a3,
              s2u(Qs + (m0 + (lane & 15)) * KL_P + k0 + 8 * (lane >> 4)));
#pragma unroll
        for (int p = 0; p < 4; p++) {
            int n0 = p * 16;
            uint32_t b0, b1, b2, b3;
            ldsm4(b0, b1, b2, b3,
                  s2u(Ks + (n0 + (lane & 7) + 8 * (lane >> 4)) * KL_P
                         + k0 + 8 * ((lane >> 3) & 1)));
            mma16(acc[2 * p    ], a0, a1, a2, a3, b0, b1);
            mma16(acc[2 * p + 1], a0, a1, a2, a3, b2, b3);
        }
    }

    float mx0 = -1e30f, mx1 = -1e30f;
#pragma unroll
    for (int nt = 0; nt < 8; nt++) {
        mx0 = fmaxf(mx0, fmaxf(acc[nt][0], acc[nt][1]));
        mx1 = fmaxf(mx1, fmaxf(acc[nt][2], acc[nt][3]));
    }
    mx0 = fmaxf(mx0, __shfl_xor_sync(0xffffffffu, mx0, 1));
    mx0 = fmaxf(mx0, __shfl_xor_sync(0xffffffffu, mx0, 2));
    mx1 = fmaxf(mx1, __shfl_xor_sync(0xffffffffu, mx1, 1));
    mx1 = fmaxf(mx1, __shfl_xor_sync(0xffffffffu, mx1, 2));
    float nm0 = -mx0 * SCALE2_, nm1 = -mx1 * SCALE2_;
    float s0 = 0.f, s1 = 0.f;
#pragma unroll
    for (int nt = 0; nt < 8; nt++) {
        acc[nt][0] = exp2f(fmaf(acc[nt][0], SCALE2_, nm0)); s0 += acc[nt][0];
        acc[nt][1] = exp2f(fmaf(acc[nt][1], SCALE2_, nm0)); s0 += acc[nt][1];
        acc[nt][2] = exp2f(fmaf(acc[nt][2], SCALE2_, nm1)); s1 += acc[nt][2];
        acc[nt][3] = exp2f(fmaf(acc[nt][3], SCALE2_, nm1)); s1 += acc[nt][3];
    }
    s0 += __shfl_xor_sync(0xffffffffu, s0, 1);
    s0 += __shfl_xor_sync(0xffffffffu, s0, 2);
    s1 += __shfl_xor_sync(0xffffffffu, s1, 1);
    s1 += __shfl_xor_sync(0xffffffffu, s1, 2);
    float inv0 = 1.0f / s0, inv1 = 1.0f / s1;

    __syncthreads();   // all warps done with Ks (Kbar) reads before overwrite

#pragma unroll
    for (int nt = 0; nt < 8; nt++) {
        int col = nt * 8 + 2 * t;
        *(__half2*)(Lh + (m0 + g    ) * KL_P + col) =
            __floats2half2_rn(acc[nt][0] * inv0, acc[nt][1] * inv0);
        *(__half2*)(Lh + (m0 + g + 8) * KL_P + col) =
            __floats2half2_rn(acc[nt][2] * inv1, acc[nt][3] * inv1);
    }
    __syncthreads();

    if (writeL) {
        __half* Lg = g_LBUF + ((size_t)bh * BB_ + l) * M_ * M_;
        for (int idx = tid; idx < 64 * 8; idx += 128) {
            int i = idx >> 3, sg = idx & 7;
            *(uint4*)(Lg + idx * 8) = *(uint4*)(Lh + i * KL_P + sg * 8);
        }
    }

    // GEMM2 + ones-column w
    float acc2[8][4];
    float accw[4] = {0.f, 0.f, 0.f, 0.f};
#pragma unroll
    for (int nt = 0; nt < 8; nt++)
#pragma unroll
        for (int e = 0; e < 4; e++) acc2[nt][e] = 0.f;

#pragma unroll
    for (int s = 0; s < 4; s++) {
        int i0 = s * 16;
        uint32_t a0, a1, a2, a3;
        ldsm4t(a0, a1, a2, a3,
               s2u(Lh + (i0 + (lane & 7) + 8 * (lane >> 4)) * KL_P
                      + m0 + 8 * ((lane >> 3) & 1)));
#pragma unroll
        for (int p = 0; p < 4; p++) {
            int n0 = p * 16;
            uint32_t b0, b1, b2, b3;
            ldsm4t(b0, b1, b2, b3,
                   s2u(Qs + (i0 + (lane & 7) + 8 * ((lane >> 3) & 1)) * KL_P
                          + n0 + 8 * (lane >> 4)));
            mma16(acc2[2 * p    ], a0, a1, a2, a3, b0, b1);
            mma16(acc2[2 * p + 1], a0, a1, a2, a3, b2, b3);
        }
        uint32_t w0, w1;
        ldsm2t(w0, w1,
               s2u(Qs + (i0 + (lane & 7) + 8 * ((lane >> 3) & 1)) * KL_P + 64));
        mma16(accw, a0, a1, a2, a3, w0, w1);
    }

    float wr0 = __shfl_sync(0xffffffffu, accw[0], lane & 28);
    float wr1 = __shfl_sync(0xffffffffu, accw[2], lane & 28);
    float w0 = 1.0f / (wr0 + EPS_), w1 = 1.0f / (wr1 + EPS_);

    __half* Qbg = g_QBAR + (size_t)bh * M_ * BB_ * D_ + (size_t)l * D_;
#pragma unroll
    for (int nt = 0; nt < 8; nt++) {
        int dd = nt * 8 + 2 * t;
        *(__half2*)(Qbg + (size_t)(m0 + g    ) * BB_ * D_ + dd) =
            __floats2half2_rn(acc2[nt][0] * w0, acc2[nt][1] * w0);
        *(__half2*)(Qbg + (size_t)(m0 + g + 8) * BB_ * D_ + dd) =
            __floats2half2_rn(acc2[nt][2] * w1, acc2[nt][3] * w1);
    }
}

// ---------------------------------------------------------------------------
// kr: 256 threads, 8 warps, P in registers, V prefetched via second cp.async
// group into fp32 staging smem.  grid (64, 64)
// ---------------------------------------------------------------------------
#define KR_P 72

__global__ __launch_bounds__(256, 3)
void kr_kernel(const float* __restrict__ V, int last)
{
    __shared__ __half Qbs[BB_ * KR_P];
    __shared__ __half Ks [BB_ * KR_P];   // K_k; overwritten by V_k on last iter
    __shared__ float  Vf [BB_ * D_];     // fp32 V staging (last iter only)

    int k  = blockIdx.x;
    int bh = blockIdx.y;
    int tid = threadIdx.x;
    int lane = tid & 31, wid = tid >> 5;
    int g = lane >> 2, t = lane & 3;

    const __half* Qbg = g_QBAR + ((size_t)bh * M_ + k) * BB_ * D_;
    for (int idx = tid; idx < BB_ * 8; idx += 256) {
        int r = idx >> 3, sg = idx & 7;
        cpa16(s2u(Qbs + r * KR_P + sg * 8), Qbg + idx * 8);
    }
    const __half* Kg = g_Kh + ((size_t)bh * N_ + (size_t)k * BB_) * D_;
    for (int idx = tid; idx < BB_ * 8; idx += 256) {
        int r = idx >> 3, sg = idx & 7;
        cpa16(s2u(Ks + r * KR_P + sg * 8), Kg + idx * 8);
    }
    cpa_commit();
    if (last) {
        const float* Vg = V + ((size_t)bh * N_ + (size_t)k * BB_) * D_;
        for (int idx = tid; idx < BB_ * 16; idx += 256)
            cpa16(s2u(Vf + idx * 4), Vg + idx * 4);
        cpa_commit();
        cpa_wait1();
    } else {
        cpa_wait0();
    }
    __syncthreads();

    int m0 = wid * 16;

    float acc1[16][4];
#pragma unroll
    for (int nt = 0; nt < 16; nt++)
#pragma unroll
        for (int e = 0; e < 4; e++) acc1[nt][e] = 0.f;

#pragma unroll
    for (int s = 0; s < 4; s++) {
        int k0 = s * 16;
        uint32_t a0, a1, a2, a3;
        ldsm4(a0, a1, a2, a3,
              s2u(Qbs + (m0 + (lane & 15)) * KR_P + k0 + 8 * (lane >> 4)));
#pragma unroll
        for (int p = 0; p < 8; p++) {
            int n0 = p * 16;
            uint32_t b0, b1, b2, b3;
            ldsm4(b0, b1, b2, b3,
                  s2u(Ks + (n0 + (lane & 7) + 8 * (lane >> 4)) * KR_P
                         + k0 + 8 * ((lane >> 3) & 1)));
            mma16(acc1[2 * p    ], a0, a1, a2, a3, b0, b1);
            mma16(acc1[2 * p + 1], a0, a1, a2, a3, b2, b3);
        }
    }

    if (last) {
        __syncthreads();       // all warps done reading Ks
        cpa_wait0();           // V staging complete
        for (int idx = tid; idx < BB_ * 16; idx += 256) {
            int r = idx >> 4, d4 = idx & 15;
            float4 v = *(const float4*)(Vf + r * D_ + d4 * 4);
            uint2 u; u.x = packh2(v.x, v.y); u.y = packh2(v.z, v.w);
            *(uint2*)(Ks + r * KR_P + d4 * 4) = u;
        }
        __syncthreads();
    }

    float mx0 = -1e30f, mx1 = -1e30f;
#pragma unroll
    for (int nt = 0; nt < 16; nt++) {
        mx0 = fmaxf(mx0, fmaxf(acc1[nt][0], acc1[nt][1]));
        mx1 = fmaxf(mx1, fmaxf(acc1[nt][2], acc1[nt][3]));
    }
    mx0 = fmaxf(mx0, __shfl_xor_sync(0xffffffffu, mx0, 1));
    mx0 = fmaxf(mx0, __shfl_xor_sync(0xffffffffu, mx0, 2));
    mx1 = fmaxf(mx1, __shfl_xor_sync(0xffffffffu, mx1, 1));
    mx1 = fmaxf(mx1, __shfl_xor_sync(0xffffffffu, mx1, 2));
    float nm0 = -mx0 * SCALE2_, nm1 = -mx1 * SCALE2_;
    float s0 = 0.f, s1 = 0.f;
#pragma unroll
    for (int nt = 0; nt < 16; nt++) {
        acc1[nt][0] = exp2f(fmaf(acc1[nt][0], SCALE2_, nm0)); s0 += acc1[nt][0];
        acc1[nt][1] = exp2f(fmaf(acc1[nt][1], SCALE2_, nm0)); s0 += acc1[nt][1];
        acc1[nt][2] = exp2f(fmaf(acc1[nt][2], SCALE2_, nm1)); s1 += acc1[nt][2];
        acc1[nt][3] = exp2f(fmaf(acc1[nt][3], SCALE2_, nm1)); s1 += acc1[nt][3];
    }
    s0 += __shfl_xor_sync(0xffffffffu, s0, 1);
    s0 += __shfl_xor_sync(0xffffffffu, s0, 2);
    s1 += __shfl_xor_sync(0xffffffffu, s1, 1);
    s1 += __shfl_xor_sync(0xffffffffu, s1, 2);
    float inv0 = 1.0f / s0, inv1 = 1.0f / s1;

    uint32_t prob[8][4];
#pragma unroll
    for (int s = 0; s < 8; s++) {
        prob[s][0] = packh2(acc1[2*s  ][0] * inv0, acc1[2*s  ][1] * inv0);
        prob[s][1] = packh2(acc1[2*s  ][2] * inv1, acc1[2*s  ][3] * inv1);
        prob[s][2] = packh2(acc1[2*s+1][0] * inv0, acc1[2*s+1][1] * inv0);
        prob[s][3] = packh2(acc1[2*s+1][2] * inv1, acc1[2*s+1][3] * inv1);
    }

    float acc2[8][4];
#pragma unroll
    for (int nt = 0; nt < 8; nt++)
#pragma unroll
        for (int e = 0; e < 4; e++) acc2[nt][e] = 0.f;

#pragma unroll
    for (int s = 0; s < 8; s++) {
        int i0 = s * 16;
#pragma unroll
        for (int p = 0; p < 4; p++) {
            int n0 = p * 16;
            uint32_t b0, b1, b2, b3;
            ldsm4t(b0, b1, b2, b3,
                   s2u(Ks + (i0 + (lane & 7) + 8 * ((lane >> 3) & 1)) * KR_P
                          + n0 + 8 * (lane >> 4)));
            mma16(acc2[2 * p    ], prob[s][0], prob[s][1], prob[s][2], prob[s][3], b0, b1);
            mma16(acc2[2 * p + 1], prob[s][0], prob[s][1], prob[s][2], prob[s][3], b2, b3);
        }
    }

    __half* dst = (last ? g_VBAR : g_KBAR) + ((size_t)bh * BB_ * M_ + k) * D_;
#pragma unroll
    for (int nt = 0; nt < 8; nt++) {
        int dd = nt * 8 + 2 * t;
        *(__half2*)(dst + (size_t)(m0 + g    ) * M_ * D_ + dd) =
            __floats2half2_rn(acc2[nt][0], acc2[nt][1]);
        *(__half2*)(dst + (size_t)(m0 + g + 8) * M_ * D_ + dd) =
            __floats2half2_rn(acc2[nt][2], acc2[nt][3]);
    }
}

// ---------------------------------------------------------------------------
// out: per (bh,l): out[i][d] = sum_kb L[i][kb] * Vbar[kb][d]
// grid (128, 64), 256 threads (8 warps 4x2)
// ---------------------------------------------------------------------------
#define OUT_P 72

__global__ __launch_bounds__(256)
void out_kernel(float* __restrict__ O)
{
    __shared__ __half Lsm[64 * OUT_P];
    __shared__ __half Vbs[64 * OUT_P];

    int l  = blockIdx.x;
    int bh = blockIdx.y;
    int tid = threadIdx.x;
    int lane = tid & 31, wid = tid >> 5;
    int g = lane >> 2, t = lane & 3;

    const __half* Lg = g_LBUF + ((size_t)bh * BB_ + l) * M_ * M_;
    for (int idx = tid; idx < 64 * 8; idx += 256) {
        int i = idx >> 3, sg = idx & 7;
        cpa16(s2u(Lsm + i * OUT_P + sg * 8), Lg + idx * 8);
    }
    const __half* Vg = g_VBAR + ((size_t)bh * BB_ + l) * M_ * D_;
    for (int idx = tid; idx < 64 * 8; idx += 256) {
        int i = idx >> 3, sg = idx & 7;
        cpa16(s2u(Vbs + i * OUT_P + sg * 8), Vg + idx * 8);
    }
    cpa_commit();
    cpa_wait0();
    __syncthreads();

    int wr = wid >> 1, wc = wid & 1;
    int m0 = wr * 16;

    float acc[4][4];
#pragma unroll
    for (int nt = 0; nt < 4; nt++)
#pragma unroll
        for (int e = 0; e < 4; e++) acc[nt][e] = 0.f;

#pragma unroll
    for (int s = 0; s < 4; s++) {
        int k0 = s * 16;
        uint32_t a0, a1, a2, a3;
        ldsm4(a0, a1, a2, a3,
              s2u(Lsm + (m0 + (lane & 15)) * OUT_P + k0 + 8 * (lane >> 4)));
#pragma unroll
        for (int p = 0; p < 2; p++) {
            int n0 = wc * 32 + p * 16;
            uint32_t b0, b1, b2, b3;
            ldsm4t(b0, b1, b2, b3,
                   s2u(Vbs + (k0 + (lane & 7) + 8 * ((lane >> 3) & 1)) * OUT_P
                           + n0 + 8 * (lane >> 4)));
            mma16(acc[2 * p    ], a0, a1, a2, a3, b0, b1);
            mma16(acc[2 * p + 1], a0, a1, a2, a3, b2, b3);
        }
    }

    float* Og = O + (size_t)bh * N_ * D_ + (size_t)l * D_;
#pragma unroll
    for (int nt = 0; nt < 4; nt++) {
        int dd = wc * 32 + nt * 8 + 2 * t;
        *(float2*)(Og + (size_t)(m0 + g    ) * BB_ * D_ + dd) =
            make_float2(acc[nt][0], acc[nt][1]);
        *(float2*)(Og + (size_t)(m0 + g + 8) * BB_ * D_ + dd) =
            make_float2(acc[nt][2], acc[nt][3]);
    }
}

// ---------------------------------------------------------------------------
extern "C" void kernel_launch(void* const* d_in, const int* in_sizes, int n_in,
                              void* d_out, int out_size)
{
    const float* Q = (const float*)d_in[0];
    const float* K = (const float*)d_in[1];
    const float* V = (const float*)d_in[2];
    float* O = (float*)d_out;

    dim3 blk256(256), blk128(128);
    initqk_kernel<<<dim3(M_, BH_), blk256>>>(Q, K);
    for (int t = 0; t < NSTEPS_; t++) {
        int lastFlag = (t == NSTEPS_ - 1) ? 1 : 0;
        kl_kernel<<<dim3(BB_, BH_), blk128>>>(lastFlag);
        kr_kernel<<<dim3(M_, BH_), blk256>>>(V, lastFlag);
    }
    out_kernel<<<dim3(BB_, BH_), blk256>>>(O);
}